// round 1
// baseline (speedup 1.0000x reference)
#include <cuda_runtime.h>
#include <cuda_bf16.h>
#include <cstdint>

#define BUFW  144
#define WARPS 4
#define RPW   4
#define ROWS_PER_CTA (WARPS * RPW)

// Epilogue segment descriptors: 31 segments of 8 floats after the 64 hb outputs.
// kind: 0=pos_emb 1=action_emb 2=active_emb 3=street_emb 4=num_players_emb 5=blind_emb 6=proj
__constant__ int c_kind[31] = {3,0,2,2,2,2,2,0,0,0,0,0,6,6,6,6,0,1,5,6,1,0,5,4,0,6,6,6,6,6,6};
__constant__ int c_col[31]  = {18,20,22,23,24,25,26,27,28,29,30,31,0,1,2,3,35,36,37,4,32,33,34,19,38,5,6,7,8,9,10};
__constant__ int c_scol[11] = {40,41,42,43,39,44,45,46,47,48,49};
__constant__ int c_widx[11] = {0,2,3,5,1,4,4,4,4,4,4};

struct Params {
    const float *state;
    const float *suit, *rank;
    const float *hW1,*hb1,*hW2,*hb2,*hW3,*hb3;
    const float *bW1,*bb1,*bW2,*bb2,*bW3,*bb3;
    const float *cW1,*cb1,*cW2,*cb2,*cW3,*cb3;
    const float *pos,*action,*active,*street,*nump,*blind;
    const float *sW,*sb;
    float *out;
    int nrows;
};

__device__ __forceinline__ float leaky(float v) { return v > 0.0f ? v : 0.01f * v; }

// Y[r][0..Nout) = (ACT? leaky : id)(X[r][0..Nin) @ W + b), for RPW rows per warp.
// Each lane owns column pair (jb + 2*lane, jb + 2*lane + 1). Nin, Nout even.
template <bool ACT>
__device__ __forceinline__ void mlp_layer(const float* __restrict__ W,
                                          const float* __restrict__ b,
                                          const float* xs, float* ys,
                                          int Nin, int Nout, int lane)
{
    __syncwarp();
    for (int jb = 0; jb < Nout; jb += 64) {
        int j0 = jb + 2 * lane;
        if (j0 < Nout) {
            float2 bias = __ldg((const float2*)(b + j0));
            float2 acc[RPW];
#pragma unroll
            for (int r = 0; r < RPW; r++) acc[r] = bias;
            for (int k = 0; k < Nin; k += 2) {
                float2 w0 = __ldg((const float2*)(W + (size_t)k * Nout + j0));
                float2 w1 = __ldg((const float2*)(W + (size_t)(k + 1) * Nout + j0));
#pragma unroll
                for (int r = 0; r < RPW; r++) {
                    float2 xv = *(const float2*)(xs + r * BUFW + k);
                    acc[r].x = fmaf(xv.x, w0.x, acc[r].x);
                    acc[r].y = fmaf(xv.x, w0.y, acc[r].y);
                    acc[r].x = fmaf(xv.y, w1.x, acc[r].x);
                    acc[r].y = fmaf(xv.y, w1.y, acc[r].y);
                }
            }
#pragma unroll
            for (int r = 0; r < RPW; r++) {
                float2 v = acc[r];
                if (ACT) { v.x = leaky(v.x); v.y = leaky(v.y); }
                *(float2*)(ys + r * BUFW + j0) = v;
            }
        }
    }
    __syncwarp();
}

__global__ void __launch_bounds__(WARPS * 32)
preproc_kernel(Params p)
{
    __shared__ __align__(16) float sA[WARPS][RPW][BUFW];
    __shared__ __align__(16) float sB[WARPS][RPW][BUFW];
    __shared__ __align__(16) float sC[WARPS][RPW][BUFW];

    const int warp = threadIdx.x >> 5;
    const int lane = threadIdx.x & 31;
    const int row0 = (blockIdx.x * WARPS + warp) * RPW;

    float* A = &sA[warp][0][0];
    float* B = &sB[warp][0][0];
    float* C = &sC[warp][0][0];

    // ---------- hand gather: A[r][0..63] ----------
#pragma unroll
    for (int r = 0; r < RPW; r++) {
        int row = row0 + r;
        if (row >= p.nrows) continue;
        const float* st = p.state + (size_t)row * 50;
        int e = lane;
#pragma unroll
        for (int ii = 0; ii < 2; ii++, e += 32) {
            int c = e >> 4, w = e & 15, d = e & 7;
            int col = (w < 8) ? (2 * c + 1) : (2 * c);     // suit col : rank col
            int iv = (int)st[col];
            A[r * BUFW + e] = (w < 8) ? __ldg(p.suit + iv * 8 + d)
                                      : __ldg(p.rank + iv * 8 + d);
        }
    }

    // hand MLP: 64 -> 64 -> 64 -> 64 (last layer no act) -> C[0..63]
    mlp_layer<true >(p.hW1, p.hb1, A, B, 64, 64, lane);
    mlp_layer<true >(p.hW2, p.hb2, B, A, 64, 64, lane);
    mlp_layer<false>(p.hW3, p.hb3, A, C, 64, 64, lane);

    // ---------- board gather: A[r][0..79] ----------
#pragma unroll
    for (int r = 0; r < RPW; r++) {
        int row = row0 + r;
        if (row >= p.nrows) continue;
        const float* st = p.state + (size_t)row * 50;
        int e = lane;
#pragma unroll
        for (int ii = 0; ii < 3; ii++, e += 32) {
            if (e < 80) {
                int c = e >> 4, w = e & 15, d = e & 7;
                int col = (w < 8) ? (9 + 2 * c) : (8 + 2 * c);
                int iv = (int)st[col];
                A[r * BUFW + e] = (w < 8) ? __ldg(p.suit + iv * 8 + d)
                                          : __ldg(p.rank + iv * 8 + d);
            }
        }
    }

    // board MLP: 80 -> 80 -> 80 -> 80 -> C[64..143]
    mlp_layer<true >(p.bW1, p.bb1, A, B, 80, 80, lane);
    mlp_layer<true >(p.bW2, p.bb2, B, A, 80, 80, lane);
    mlp_layer<false>(p.bW3, p.bb3, A, C + 64, 80, 80, lane);

    // hand_board MLP: 144 -> 144 -> 64 -> 64
    mlp_layer<true >(p.cW1, p.cb1, C, A, 144, 144, lane);
    mlp_layer<true >(p.cW2, p.cb2, A, B, 144, 64, lane);
    mlp_layer<false>(p.cW3, p.cb3, B, C, 64, 64, lane);

    // ---------- write hb output + epilogue ----------
    const float* tabs[6] = { p.pos, p.action, p.active, p.street, p.nump, p.blind };

#pragma unroll
    for (int r = 0; r < RPW; r++) {
        int row = row0 + r;
        if (row >= p.nrows) continue;
        float* orow = p.out + (size_t)row * 312;
        // hb result (cols 0..63)
        int j = 2 * lane;
        *(float2*)(orow + j) = *(const float2*)(C + r * BUFW + j);

        // 248 remaining features (cols 64..311)
        const float* st = p.state + (size_t)row * 50;
        for (int t = lane; t < 248; t += 32) {
            int s = t >> 3, d = t & 7;
            int kind = c_kind[s], col = c_col[s];
            float v;
            if (kind == 6) {
                float sc = st[c_scol[col]];
                int w = c_widx[col];
                v = fmaf(sc, __ldg(p.sW + w * 8 + d), __ldg(p.sb + w * 8 + d));
            } else {
                int iv = (int)st[col];
                v = __ldg(tabs[kind] + iv * 8 + d);
            }
            orow[64 + t] = v;
        }
    }
}

extern "C" void kernel_launch(void* const* d_in, const int* in_sizes, int n_in,
                              void* d_out, int out_size)
{
    Params p;
    p.state  = (const float*)d_in[0];
    p.suit   = (const float*)d_in[1];
    p.rank   = (const float*)d_in[2];
    p.hW1 = (const float*)d_in[3];  p.hb1 = (const float*)d_in[4];
    p.hW2 = (const float*)d_in[5];  p.hb2 = (const float*)d_in[6];
    p.hW3 = (const float*)d_in[7];  p.hb3 = (const float*)d_in[8];
    p.bW1 = (const float*)d_in[9];  p.bb1 = (const float*)d_in[10];
    p.bW2 = (const float*)d_in[11]; p.bb2 = (const float*)d_in[12];
    p.bW3 = (const float*)d_in[13]; p.bb3 = (const float*)d_in[14];
    p.cW1 = (const float*)d_in[15]; p.cb1 = (const float*)d_in[16];
    p.cW2 = (const float*)d_in[17]; p.cb2 = (const float*)d_in[18];
    p.cW3 = (const float*)d_in[19]; p.cb3 = (const float*)d_in[20];
    p.pos    = (const float*)d_in[21];
    p.action = (const float*)d_in[22];
    p.active = (const float*)d_in[23];
    p.street = (const float*)d_in[24];
    p.nump   = (const float*)d_in[25];
    p.blind  = (const float*)d_in[26];
    p.sW     = (const float*)d_in[27];
    p.sb     = (const float*)d_in[28];
    p.out    = (float*)d_out;
    p.nrows  = out_size / 312;

    int grid = (p.nrows + ROWS_PER_CTA - 1) / ROWS_PER_CTA;
    preproc_kernel<<<grid, WARPS * 32>>>(p);
}